// round 16
// baseline (speedup 1.0000x reference)
#include <cuda_runtime.h>
#include <cuda_bf16.h>
#include <math.h>
#include <float.h>
#include <stdint.h>

#define NPIX 131072
#define DIMC 720
#define HWSZ 32768
#define WID 256
#define KCLS 19
#define MPROT 10
#define JTOT 190
#define NTILE 1024              // pixel tiles of 128
#define NKC 12                  // 64-wide k chunks (720 -> 768)
#define ABLK 16384              // bytes per (tn, kc) fragment block: 8 mtiles * 4 ktiles * 512B
#define BFRAG_BYTES (24 * 48 * 256)

// ---------------- device scratch ----------------
// A fragments: [tn][kc][tmL 0..7][tkL 0..3][lane 0..31][16B]  (mma m16n8k16 A-frag order)
__device__ __align__(16) unsigned char g_cAhi[(size_t)NTILE * NKC * ABLK];
__device__ __align__(16) unsigned char g_cAlo[(size_t)NTILE * NKC * ABLK];
// B fragments: [jt 0..23][tk 0..47][lane 0..31][8B]
__device__ __align__(16) unsigned char g_Bhi[BFRAG_BYTES];
__device__ __align__(16) unsigned char g_Blo[BFRAG_BYTES];
__device__ float g_Pn[JTOT * DIMC];
__device__ float g_scal[3];
__device__ float g_mu[NPIX], g_is[NPIX], g_sc[NPIX];
__device__ float g_S[KCLS];
__device__ int   g_Bk[KCLS];
__device__ float g_R[3 * JTOT];
__device__ float g_a[JTOT];
__device__ float g_b[NPIX];
__device__ unsigned char g_corr[NPIX];
__device__ unsigned char g_m[NPIX];
__device__ float g_f[JTOT * DIMC];
__device__ int   g_cnt[JTOT];

// ---------------- helpers ----------------
__device__ __forceinline__ void mma16816(float* d, const uint32_t* a, const uint32_t* b) {
    asm volatile(
        "mma.sync.aligned.m16n8k16.row.col.f32.bf16.bf16.f32 "
        "{%0,%1,%2,%3}, {%4,%5,%6,%7}, {%8,%9}, {%0,%1,%2,%3};"
        : "+f"(d[0]), "+f"(d[1]), "+f"(d[2]), "+f"(d[3])
        : "r"(a[0]), "r"(a[1]), "r"(a[2]), "r"(a[3]), "r"(b[0]), "r"(b[1]));
}

__device__ __forceinline__ float block_reduce_256(float v, float* red) {
    int t = threadIdx.x;
    __syncthreads();
    red[t] = v;
    __syncthreads();
    #pragma unroll
    for (int s = 128; s > 0; s >>= 1) {
        if (t < s) red[t] += red[t + s];
        __syncthreads();
    }
    return red[0];
}

// fragment byte offset inside a (tn,kc) A block, for local pixel nl (0-127), local dim dl (0-63)
__device__ __forceinline__ uint32_t afrag_off(int nl, int dl) {
    int tmL = nl >> 4, rm = nl & 15;
    int tkL = dl >> 4, kcc = dl & 15;
    int lane = (rm & 7) * 4 + ((kcc & 7) >> 1);
    int reg = (rm >> 3) | ((kcc >> 3) << 1);
    return (uint32_t)((tmL * 4 + tkL) * 512 + lane * 16 + reg * 4 + (kcc & 1) * 2);
}

// ---------------- kernels ----------------
__global__ void k_zero() {
    int i = blockIdx.x * 256 + threadIdx.x;
    if (i < JTOT * DIMC) g_f[i] = 0.f;
    if (i < BFRAG_BYTES / 4) { ((uint32_t*)g_Bhi)[i] = 0u; ((uint32_t*)g_Blo)[i] = 0u; }
    if (i < JTOT) g_cnt[i] = 0;
    if (i < 3 * JTOT) g_R[i] = 0.f;
    if (i < KCLS) { g_S[i] = 0.f; g_Bk[i] = 0; }
}

__global__ void k_prep_scal(const float* __restrict__ g, const float* __restrict__ b) {
    __shared__ float red[256];
    int t = threadIdx.x;
    float s0 = 0.f, s1 = 0.f, s2 = 0.f;
    for (int d = t; d < DIMC; d += 256) {
        float gv = g[d], bv = b[d];
        s0 += gv * gv; s1 += gv * bv; s2 += bv * bv;
    }
    float r0 = block_reduce_256(s0, red);
    float r1 = block_reduce_256(s1, red);
    float r2 = block_reduce_256(s2, red);
    if (t == 0) { g_scal[0] = r0; g_scal[1] = r1; g_scal[2] = r2; }
}

// normalize protos -> g_Pn + B fragments (hi/lo).  B[d][j] = protos_n[j][d], col-major frag.
__global__ void k_prep_protos(const float* __restrict__ P) {
    __shared__ float red[256];
    int j = blockIdx.x, t = threadIdx.x;
    float ss = 0.f;
    for (int d = t; d < DIMC; d += 256) { float v = P[j * DIMC + d]; ss += v * v; }
    float nrm = sqrtf(block_reduce_256(ss, red));
    float inv = 1.f / fmaxf(nrm, 1e-12f);
    int jt = j >> 3, gj = j & 7;
    for (int d = t; d < DIMC; d += 256) {
        float v = P[j * DIMC + d] * inv;
        g_Pn[j * DIMC + d] = v;
        __nv_bfloat16 h = __float2bfloat16(v);
        __nv_bfloat16 l = __float2bfloat16(v - __bfloat162float(h));
        int tk = d >> 4, kcc = d & 15;
        int lane = gj * 4 + ((kcc & 7) >> 1);
        int reg = (kcc >> 3) & 1;
        uint32_t off = (uint32_t)(((jt * 48 + tk) * 32 + lane) * 8 + reg * 4 + (kcc & 1) * 2);
        *(__nv_bfloat16*)(g_Bhi + off) = h;
        *(__nv_bfloat16*)(g_Blo + off) = l;
    }
}

// per-pixel LN stats + post-LN l2 scale
__global__ void k_stats(const float* __restrict__ c,
                        const float* __restrict__ gam, const float* __restrict__ bet) {
    __shared__ float sg[DIMC], sb[DIMC];
    int t = threadIdx.x;
    for (int d = t; d < DIMC; d += blockDim.x) { sg[d] = gam[d]; sb[d] = bet[d]; }
    __syncthreads();
    int n = blockIdx.x * blockDim.x + t;
    int b = n >> 15, hw = n & (HWSZ - 1);
    const float* base = c + (size_t)b * DIMC * HWSZ + hw;
    float sx = 0.f, sxx = 0.f, s2x = 0.f, s2xx = 0.f, sbx = 0.f;
    for (int d = 0; d < DIMC; ++d) {
        float x = base[(size_t)d * HWSZ];
        float g = sg[d], bb = sb[d];
        float x2 = x * x;
        sx += x; sxx += x2;
        float g2 = g * g;
        s2x = fmaf(g2, x, s2x);
        s2xx = fmaf(g2, x2, s2xx);
        sbx = fmaf(g * bb, x, sbx);
    }
    float mu = sx * (1.f / DIMC);
    float var = sxx * (1.f / DIMC) - mu * mu;
    float is = 1.f / sqrtf(var + 1e-5f);
    float lnss = is * is * (s2xx - 2.f * mu * s2x + mu * mu * g_scal[0])
               + 2.f * is * (sbx - mu * g_scal[1]) + g_scal[2];
    lnss = fmaxf(lnss, 0.f);
    g_mu[n] = mu; g_is[n] = is;
    g_sc[n] = 1.f / fmaxf(sqrtf(lnss), 1e-12f);
}

// normalized features -> A fragments (hi/lo), one (tn, kc) block per CTA
__global__ void __launch_bounds__(256) k_normsplit(const float* __restrict__ c,
                                                   const float* __restrict__ gam,
                                                   const float* __restrict__ bet) {
    __shared__ __align__(16) unsigned char shi[ABLK];
    __shared__ __align__(16) unsigned char slo[ABLK];
    int tile = blockIdx.x;
    int tn = tile / NKC, kc = tile % NKC;
    int n0 = tn * 128;
    int b = n0 >> 15, hw0 = n0 & (HWSZ - 1);
    int t = threadIdx.x;
    int nl = t & 127, dh = t >> 7;
    int n = n0 + nl;
    float mu = g_mu[n], is = g_is[n], sc = g_sc[n];
    #pragma unroll 4
    for (int dd = 0; dd < 32; ++dd) {
        int dl = dh * 32 + dd;
        int d = kc * 64 + dl;
        float val = 0.f;
        if (d < DIMC) {
            float x = c[(size_t)b * DIMC * HWSZ + (size_t)d * HWSZ + hw0 + nl];
            val = ((x - mu) * is * __ldg(&gam[d]) + __ldg(&bet[d])) * sc;
        }
        __nv_bfloat16 h = __float2bfloat16(val);
        __nv_bfloat16 l = __float2bfloat16(val - __bfloat162float(h));
        uint32_t off = afrag_off(nl, dl);
        *(__nv_bfloat16*)(shi + off) = h;
        *(__nv_bfloat16*)(slo + off) = l;
    }
    __syncthreads();
    size_t tb = ((size_t)tn * NKC + kc) * ABLK;
    uint4* dh4 = (uint4*)(g_cAhi + tb);
    uint4* dl4 = (uint4*)(g_cAlo + tb);
    const uint4* sh4 = (const uint4*)shi;
    const uint4* sl4 = (const uint4*)slo;
    for (int i = t; i < ABLK / 16; i += 256) { dh4[i] = sh4[i]; dl4[i] = sl4[i]; }
}

// tensor GEMM via mma.sync (split-bf16, 3 products). CTA = 128 pix x 96 cols.
// grid = 1024 pixel-tiles x 2 col-halves. warp = 2 m16 tiles x 6 n8 tiles.
__global__ void __launch_bounds__(256) k_gemm_mma(float* __restrict__ Cout) {
    int tid = threadIdx.x, wid = tid >> 5, lane = tid & 31;
    int cta = blockIdx.x;
    int tn = cta >> 1, jh = cta & 1;
    int mw = wid & 3;               // m-pair index: m tiles 2mw, 2mw+1
    int jw = wid >> 2;              // j-half within CTA half
    int jbase = jh * 12 + jw * 6;   // first of 6 n8 tiles

    float acc[2][6][4];
    #pragma unroll
    for (int mi = 0; mi < 2; mi++)
        #pragma unroll
        for (int jj = 0; jj < 6; jj++)
            #pragma unroll
            for (int q = 0; q < 4; q++) acc[mi][jj][q] = 0.f;

    const unsigned char* aHbase = g_cAhi + (size_t)tn * NKC * ABLK;
    const unsigned char* aLbase = g_cAlo + (size_t)tn * NKC * ABLK;

    for (int tk = 0; tk < 48; ++tk) {
        int kc = tk >> 2, tkL = tk & 3;
        uint32_t inner = (uint32_t)(tkL * 512 + lane * 16);
        uint4 ah[2], al[2];
        #pragma unroll
        for (int mi = 0; mi < 2; mi++) {
            uint32_t off = (uint32_t)kc * ABLK + (uint32_t)(mw * 2 + mi) * 2048 + inner;
            ah[mi] = *(const uint4*)(aHbase + off);
            al[mi] = *(const uint4*)(aLbase + off);
        }
        uint2 bh[6], bl[6];
        #pragma unroll
        for (int jj = 0; jj < 6; jj++) {
            uint32_t off = (uint32_t)(((jbase + jj) * 48 + tk) * 256 + lane * 8);
            bh[jj] = *(const uint2*)(g_Bhi + off);
            bl[jj] = *(const uint2*)(g_Blo + off);
        }
        #pragma unroll
        for (int mi = 0; mi < 2; mi++) {
            #pragma unroll
            for (int jj = 0; jj < 6; jj++) {
                mma16816(acc[mi][jj], (const uint32_t*)&ah[mi], (const uint32_t*)&bh[jj]);
                mma16816(acc[mi][jj], (const uint32_t*)&al[mi], (const uint32_t*)&bh[jj]);
                mma16816(acc[mi][jj], (const uint32_t*)&ah[mi], (const uint32_t*)&bl[jj]);
            }
        }
    }

    int g = lane >> 2, tig = lane & 3;
    #pragma unroll
    for (int mi = 0; mi < 2; mi++) {
        int row0 = tn * 128 + (mw * 2 + mi) * 16 + g;
        #pragma unroll
        for (int jj = 0; jj < 6; jj++) {
            int col = (jbase + jj) * 8 + tig * 2;
            if (col < JTOT) {
                Cout[(size_t)row0 * JTOT + col] = acc[mi][jj][0];
                Cout[(size_t)(row0 + 8) * JTOT + col] = acc[mi][jj][2];
                if (col + 1 < JTOT) {
                    Cout[(size_t)row0 * JTOT + col + 1] = acc[mi][jj][1];
                    Cout[(size_t)(row0 + 8) * JTOT + col + 1] = acc[mi][jj][3];
                }
            }
        }
    }
}

// per-pixel head
__global__ void k_head(const float* __restrict__ logits, const int* __restrict__ gt,
                       const float* __restrict__ mg, const float* __restrict__ mb,
                       float* __restrict__ out_seg) {
    __shared__ float rows[8][192];
    int warp = threadIdx.x >> 5, lane = threadIdx.x & 31;
    int n = blockIdx.x * 8 + warp;
    const float* lr = logits + (size_t)n * JTOT;
    #pragma unroll
    for (int i = 0; i < 6; i++) {
        int j = lane + 32 * i;
        if (j < JTOT) rows[warp][j] = lr[j];
    }
    __syncwarp();
    float mx = -FLT_MAX;
    if (lane < KCLS) {
        #pragma unroll
        for (int m = 0; m < MPROT; m++) mx = fmaxf(mx, rows[warp][lane * MPROT + m]);
    }
    float xv = (lane < KCLS) ? mx : 0.f;
    float s = xv, s2 = xv * xv;
    #pragma unroll
    for (int off = 16; off; off >>= 1) {
        s  += __shfl_xor_sync(0xffffffffu, s, off);
        s2 += __shfl_xor_sync(0xffffffffu, s2, off);
    }
    float mu = s * (1.f / KCLS);
    float var = s2 * (1.f / KCLS) - mu * mu;
    float isd = 1.f / sqrtf(var + 1e-5f);
    float o = -FLT_MAX;
    if (lane < KCLS) {
        o = (mx - mu) * isd * __ldg(&mg[lane]) + __ldg(&mb[lane]);
        int b = n >> 15, h = (n >> 8) & 127, w = n & 255;
        out_seg[(((size_t)b * KCLS + lane) * 128 + h) * WID + w] = o;
    }
    float bv = o; int bi = lane;
    #pragma unroll
    for (int off = 16; off; off >>= 1) {
        float ov = __shfl_xor_sync(0xffffffffu, bv, off);
        int   oi = __shfl_xor_sync(0xffffffffu, bi, off);
        if (ov > bv || (ov == bv && oi < bi)) { bv = ov; bi = oi; }
    }
    if (lane == 0) g_corr[n] = (bi == gt[n]) ? 1 : 0;
}

__global__ void k_sh_init(const float* __restrict__ logits, const int* __restrict__ gt) {
    __shared__ float sS[KCLS];
    __shared__ int sB[KCLS];
    __shared__ float sR[JTOT];
    int t = threadIdx.x;
    if (t < KCLS) { sS[t] = 0.f; sB[t] = 0; }
    if (t < JTOT) sR[t] = 0.f;
    __syncthreads();
    int n = blockIdx.x * blockDim.x + t;
    int k = gt[n];
    const float* lr = logits + (size_t)n * JTOT + k * MPROT;
    float v[MPROT]; float sum = 0.f;
    #pragma unroll
    for (int m = 0; m < MPROT; m++) { v[m] = expf(lr[m] * 20.f); sum += v[m]; }
    atomicAdd(&sS[k], sum);
    atomicAdd(&sB[k], 1);
    #pragma unroll
    for (int m = 0; m < MPROT; m++) atomicAdd(&sR[k * MPROT + m], v[m]);
    g_b[n] = 1.f;
    __syncthreads();
    if (t < KCLS) { atomicAdd(&g_S[t], sS[t]); atomicAdd(&g_Bk[t], sB[t]); }
    if (t < JTOT) atomicAdd(&g_R[t], sR[t]);
}

__global__ void k_a(int t) {
    int j = threadIdx.x;
    if (j >= JTOT) return;
    int k = j / MPROT;
    float ap = (t == 0) ? 1.f / fmaxf(g_S[k], 1e-12f) : g_a[j];
    float rowsum = ap * g_R[t * JTOT + j];
    g_a[j] = ap / (fmaxf(rowsum, 1e-12f) * (float)MPROT);
}

__global__ void k_bR(const float* __restrict__ logits, const int* __restrict__ gt, int slot) {
    __shared__ float sR[JTOT];
    int t = threadIdx.x;
    if (t < JTOT) sR[t] = 0.f;
    __syncthreads();
    int n = blockIdx.x * blockDim.x + t;
    int k = gt[n];
    const float* lr = logits + (size_t)n * JTOT + k * MPROT;
    float v[MPROT]; float s = 0.f;
    #pragma unroll
    for (int m = 0; m < MPROT; m++) {
        v[m] = expf(lr[m] * 20.f);
        s = fmaf(v[m], __ldg(&g_a[k * MPROT + m]), s);
    }
    float b = g_b[n];
    float col = b * s;
    float Bk = fmaxf((float)g_Bk[k], 1.f);
    float nb = (col > 0.f) ? (b / fmaxf(col, 1e-12f)) / Bk : 0.f;
    g_b[n] = nb;
    #pragma unroll
    for (int m = 0; m < MPROT; m++) atomicAdd(&sR[k * MPROT + m], v[m] * nb);
    __syncthreads();
    if (t < JTOT) atomicAdd(&g_R[slot * JTOT + t], sR[t]);
}

__global__ void k_final(const float* __restrict__ logits, const int* __restrict__ gt,
                        float* __restrict__ target) {
    int n = blockIdx.x * blockDim.x + threadIdx.x;
    int k = gt[n];
    const float* lr = logits + (size_t)n * JTOT + k * MPROT;
    float best = -FLT_MAX; int bm = 0;
    #pragma unroll
    for (int m = 0; m < MPROT; m++) {
        float q = expf(lr[m] * 20.f) * __ldg(&g_a[k * MPROT + m]);
        if (q > best) { best = q; bm = m; }
    }
    g_m[n] = (unsigned char)bm;
    target[n] = (float)(bm + MPROT * k);
}

// accumulate f over correct pixels, reconstructing _c from A hi/lo fragments
__global__ void k_faccum(const int* __restrict__ gt) {
    int t = threadIdx.x;
    int base = blockIdx.x * 32;
    for (int p = 0; p < 32; p++) {
        int n = base + p;
        if (!g_corr[n]) continue;
        int j = gt[n] * MPROT + g_m[n];
        if (t == 0) atomicAdd(&g_cnt[j], 1);
        int tn = n >> 7, nl = n & 127;
        for (int d = t; d < DIMC; d += blockDim.x) {
            int kc = d >> 6, dl = d & 63;
            size_t tb = ((size_t)tn * NKC + kc) * ABLK;
            uint32_t off = afrag_off(nl, dl);
            float v = __bfloat162float(*(const __nv_bfloat16*)(g_cAhi + tb + off))
                    + __bfloat162float(*(const __nv_bfloat16*)(g_cAlo + tb + off));
            atomicAdd(&g_f[j * DIMC + d], v);
        }
    }
}

__global__ void k_proto_out(float* __restrict__ outp) {
    __shared__ float red[256];
    __shared__ float cand[DIMC];
    int j = blockIdx.x, t = threadIdx.x, k = j / MPROT;
    int cnt = g_cnt[j];
    int rs = 0;
    #pragma unroll
    for (int m = 0; m < MPROT; m++) rs += g_cnt[k * MPROT + m];
    bool upd = (cnt > 0) && (rs > 0);
    float ss = 0.f;
    for (int d = t; d < DIMC; d += 256) { float fv = g_f[j * DIMC + d]; ss += fv * fv; }
    float fn = sqrtf(block_reduce_256(ss, red));
    float finv = 1.f / fmaxf(fn, 1e-12f);
    float ss2 = 0.f;
    for (int d = t; d < DIMC; d += 256) {
        float p = g_Pn[j * DIMC + d];
        float cv = upd ? (0.999f * p + 0.001f * (g_f[j * DIMC + d] * finv)) : p;
        cand[d] = cv; ss2 += cv * cv;
    }
    float n2 = fmaxf(sqrtf(block_reduce_256(ss2, red)), 1e-12f);
    float inv2 = 1.f / n2;
    __syncthreads();
    for (int d = t; d < DIMC; d += 256) outp[j * DIMC + d] = cand[d] * inv2;
}

// ---------------- launch ----------------
extern "C" void kernel_launch(void* const* d_in, const int* in_sizes, int n_in,
                              void* d_out, int out_size) {
    const float* c  = (const float*)d_in[0];
    const int*   gt = (const int*)d_in[1];
    const float* P  = (const float*)d_in[2];
    const float* fg = (const float*)d_in[3];
    const float* fb = (const float*)d_in[4];
    const float* mg = (const float*)d_in[5];
    const float* mb = (const float*)d_in[6];

    float* out      = (float*)d_out;
    float* out_seg  = out;
    float* logits   = out + 2490368;
    float* target   = out + 2490368 + 24903680;
    float* pnew     = target + NPIX;

    k_zero<<<535, 256>>>();
    k_prep_scal<<<1, 256>>>(fg, fb);
    k_prep_protos<<<JTOT, 256>>>(P);
    k_stats<<<NPIX / 256, 256>>>(c, fg, fb);
    k_normsplit<<<NTILE * NKC, 256>>>(c, fg, fb);
    k_gemm_mma<<<NTILE * 2, 256>>>(logits);
    k_head<<<NPIX / 8, 256>>>(logits, gt, mg, mb, out_seg);
    k_sh_init<<<NPIX / 256, 256>>>(logits, gt);
    k_a<<<1, 192>>>(0);
    k_bR<<<NPIX / 256, 256>>>(logits, gt, 1);
    k_a<<<1, 192>>>(1);
    k_bR<<<NPIX / 256, 256>>>(logits, gt, 2);
    k_a<<<1, 192>>>(2);
    k_final<<<NPIX / 256, 256>>>(logits, gt, target);
    k_faccum<<<NPIX / 32, 256>>>(gt);
    k_proto_out<<<JTOT, 256>>>(pnew);
}

// round 17
// speedup vs baseline: 1.7921x; 1.7921x over previous
#include <cuda_runtime.h>
#include <cuda_bf16.h>
#include <math.h>
#include <float.h>
#include <stdint.h>

#define NPIX 131072
#define DIMC 720
#define HWSZ 32768
#define WID 256
#define KCLS 19
#define MPROT 10
#define JTOT 190
#define NTILE 1024              // pixel tiles of 128
#define NKC 12                  // 64-wide k chunks (720 -> 768)
#define ABLK 16384              // bytes per (tn, kc) fragment block: 8 mtiles * 4 ktiles * 512B
#define BFRAG_BYTES (24 * 48 * 256)
#define BCH_BYTES (12 * 1024)   // per-precision B chunk: 12 jtiles * 4 tk * 256B

// ---------------- device scratch ----------------
// A fragments: [tn][kc][tmL 0..7][tkL 0..3][lane 0..31][16B]  (mma m16n8k16 A-frag order)
__device__ __align__(16) unsigned char g_cAhi[(size_t)NTILE * NKC * ABLK];
__device__ __align__(16) unsigned char g_cAlo[(size_t)NTILE * NKC * ABLK];
// B fragments: [jt 0..23][tk 0..47][lane 0..31][8B]
__device__ __align__(16) unsigned char g_Bhi[BFRAG_BYTES];
__device__ __align__(16) unsigned char g_Blo[BFRAG_BYTES];
__device__ float g_Pn[JTOT * DIMC];
__device__ float g_scal[3];
__device__ float g_mu[NPIX], g_is[NPIX], g_sc[NPIX];
__device__ float g_S[KCLS];
__device__ int   g_Bk[KCLS];
__device__ float g_R[3 * JTOT];
__device__ float g_a[JTOT];
__device__ float g_b[NPIX];
__device__ unsigned char g_corr[NPIX];
__device__ unsigned char g_m[NPIX];
__device__ float g_f[JTOT * DIMC];
__device__ int   g_cnt[JTOT];

// ---------------- helpers ----------------
__device__ __forceinline__ void mma16816(float* d, const uint32_t* a, const uint32_t* b) {
    asm volatile(
        "mma.sync.aligned.m16n8k16.row.col.f32.bf16.bf16.f32 "
        "{%0,%1,%2,%3}, {%4,%5,%6,%7}, {%8,%9}, {%0,%1,%2,%3};"
        : "+f"(d[0]), "+f"(d[1]), "+f"(d[2]), "+f"(d[3])
        : "r"(a[0]), "r"(a[1]), "r"(a[2]), "r"(a[3]), "r"(b[0]), "r"(b[1]));
}

__device__ __forceinline__ float block_reduce_256(float v, float* red) {
    int t = threadIdx.x;
    __syncthreads();
    red[t] = v;
    __syncthreads();
    #pragma unroll
    for (int s = 128; s > 0; s >>= 1) {
        if (t < s) red[t] += red[t + s];
        __syncthreads();
    }
    return red[0];
}

// fragment byte offset inside a (tn,kc) A block, for local pixel nl (0-127), local dim dl (0-63)
__device__ __forceinline__ uint32_t afrag_off(int nl, int dl) {
    int tmL = nl >> 4, rm = nl & 15;
    int tkL = dl >> 4, kcc = dl & 15;
    int lane = (rm & 7) * 4 + ((kcc & 7) >> 1);
    int reg = (rm >> 3) | ((kcc >> 3) << 1);
    return (uint32_t)((tmL * 4 + tkL) * 512 + lane * 16 + reg * 4 + (kcc & 1) * 2);
}

// ---------------- kernels ----------------
__global__ void k_zero() {
    int i = blockIdx.x * 256 + threadIdx.x;
    if (i < JTOT * DIMC) g_f[i] = 0.f;
    if (i < BFRAG_BYTES / 4) { ((uint32_t*)g_Bhi)[i] = 0u; ((uint32_t*)g_Blo)[i] = 0u; }
    if (i < JTOT) g_cnt[i] = 0;
    if (i < 3 * JTOT) g_R[i] = 0.f;
    if (i < KCLS) { g_S[i] = 0.f; g_Bk[i] = 0; }
}

__global__ void k_prep_scal(const float* __restrict__ g, const float* __restrict__ b) {
    __shared__ float red[256];
    int t = threadIdx.x;
    float s0 = 0.f, s1 = 0.f, s2 = 0.f;
    for (int d = t; d < DIMC; d += 256) {
        float gv = g[d], bv = b[d];
        s0 += gv * gv; s1 += gv * bv; s2 += bv * bv;
    }
    float r0 = block_reduce_256(s0, red);
    float r1 = block_reduce_256(s1, red);
    float r2 = block_reduce_256(s2, red);
    if (t == 0) { g_scal[0] = r0; g_scal[1] = r1; g_scal[2] = r2; }
}

// normalize protos -> g_Pn + B fragments (hi/lo).  B[d][j] = protos_n[j][d], col-major frag.
__global__ void k_prep_protos(const float* __restrict__ P) {
    __shared__ float red[256];
    int j = blockIdx.x, t = threadIdx.x;
    float ss = 0.f;
    for (int d = t; d < DIMC; d += 256) { float v = P[j * DIMC + d]; ss += v * v; }
    float nrm = sqrtf(block_reduce_256(ss, red));
    float inv = 1.f / fmaxf(nrm, 1e-12f);
    int jt = j >> 3, gj = j & 7;
    for (int d = t; d < DIMC; d += 256) {
        float v = P[j * DIMC + d] * inv;
        g_Pn[j * DIMC + d] = v;
        __nv_bfloat16 h = __float2bfloat16(v);
        __nv_bfloat16 l = __float2bfloat16(v - __bfloat162float(h));
        int tk = d >> 4, kcc = d & 15;
        int lane = gj * 4 + ((kcc & 7) >> 1);
        int reg = (kcc >> 3) & 1;
        uint32_t off = (uint32_t)(((jt * 48 + tk) * 32 + lane) * 8 + reg * 4 + (kcc & 1) * 2);
        *(__nv_bfloat16*)(g_Bhi + off) = h;
        *(__nv_bfloat16*)(g_Blo + off) = l;
    }
}

// per-pixel LN stats + post-LN l2 scale
__global__ void k_stats(const float* __restrict__ c,
                        const float* __restrict__ gam, const float* __restrict__ bet) {
    __shared__ float sg[DIMC], sb[DIMC];
    int t = threadIdx.x;
    for (int d = t; d < DIMC; d += blockDim.x) { sg[d] = gam[d]; sb[d] = bet[d]; }
    __syncthreads();
    int n = blockIdx.x * blockDim.x + t;
    int b = n >> 15, hw = n & (HWSZ - 1);
    const float* base = c + (size_t)b * DIMC * HWSZ + hw;
    float sx = 0.f, sxx = 0.f, s2x = 0.f, s2xx = 0.f, sbx = 0.f;
    for (int d = 0; d < DIMC; ++d) {
        float x = base[(size_t)d * HWSZ];
        float g = sg[d], bb = sb[d];
        float x2 = x * x;
        sx += x; sxx += x2;
        float g2 = g * g;
        s2x = fmaf(g2, x, s2x);
        s2xx = fmaf(g2, x2, s2xx);
        sbx = fmaf(g * bb, x, sbx);
    }
    float mu = sx * (1.f / DIMC);
    float var = sxx * (1.f / DIMC) - mu * mu;
    float is = 1.f / sqrtf(var + 1e-5f);
    float lnss = is * is * (s2xx - 2.f * mu * s2x + mu * mu * g_scal[0])
               + 2.f * is * (sbx - mu * g_scal[1]) + g_scal[2];
    lnss = fmaxf(lnss, 0.f);
    g_mu[n] = mu; g_is[n] = is;
    g_sc[n] = 1.f / fmaxf(sqrtf(lnss), 1e-12f);
}

// normalized features -> A fragments (hi/lo), one (tn, kc) block per CTA
__global__ void __launch_bounds__(256) k_normsplit(const float* __restrict__ c,
                                                   const float* __restrict__ gam,
                                                   const float* __restrict__ bet) {
    __shared__ __align__(16) unsigned char shi[ABLK];
    __shared__ __align__(16) unsigned char slo[ABLK];
    int tile = blockIdx.x;
    int tn = tile / NKC, kc = tile % NKC;
    int n0 = tn * 128;
    int b = n0 >> 15, hw0 = n0 & (HWSZ - 1);
    int t = threadIdx.x;
    int nl = t & 127, dh = t >> 7;
    int n = n0 + nl;
    float mu = g_mu[n], is = g_is[n], sc = g_sc[n];
    #pragma unroll 4
    for (int dd = 0; dd < 32; ++dd) {
        int dl = dh * 32 + dd;
        int d = kc * 64 + dl;
        float val = 0.f;
        if (d < DIMC) {
            float x = c[(size_t)b * DIMC * HWSZ + (size_t)d * HWSZ + hw0 + nl];
            val = ((x - mu) * is * __ldg(&gam[d]) + __ldg(&bet[d])) * sc;
        }
        __nv_bfloat16 h = __float2bfloat16(val);
        __nv_bfloat16 l = __float2bfloat16(val - __bfloat162float(h));
        uint32_t off = afrag_off(nl, dl);
        *(__nv_bfloat16*)(shi + off) = h;
        *(__nv_bfloat16*)(slo + off) = l;
    }
    __syncthreads();
    size_t tb = ((size_t)tn * NKC + kc) * ABLK;
    uint4* dh4 = (uint4*)(g_cAhi + tb);
    uint4* dl4 = (uint4*)(g_cAlo + tb);
    const uint4* sh4 = (const uint4*)shi;
    const uint4* sl4 = (const uint4*)slo;
    for (int i = t; i < ABLK / 16; i += 256) { dh4[i] = sh4[i]; dl4[i] = sl4[i]; }
}

// tensor GEMM via mma.sync (split-bf16, 3 products). CTA = 128 pix x 96 cols.
// grid = 1024 pixel-tiles x 2 col-halves. warp = 2 m16 tiles x 6 n8 tiles.
// B (hi+lo) for the current kc chunk is staged in shared memory: 24KB coop-loaded
// once per chunk, read via conflict-free lds.64 -> kills the 2.4GB L2 B-reread
// stream that made round-16 latency-bound.
__global__ void __launch_bounds__(256) k_gemm_mma(float* __restrict__ Cout) {
    __shared__ __align__(16) unsigned char sBh[BCH_BYTES];
    __shared__ __align__(16) unsigned char sBl[BCH_BYTES];
    int tid = threadIdx.x, wid = tid >> 5, lane = tid & 31;
    int cta = blockIdx.x;
    int tn = cta >> 1, jh = cta & 1;
    int mw = wid & 3;               // m-pair index: m tiles 2mw, 2mw+1
    int jw = wid >> 2;              // j-half within CTA half
    int jloc = jw * 6;              // local jtile base (0 or 6) within this CTA's 12

    float acc[2][6][4];
    #pragma unroll
    for (int mi = 0; mi < 2; mi++)
        #pragma unroll
        for (int jj = 0; jj < 6; jj++)
            #pragma unroll
            for (int q = 0; q < 4; q++) acc[mi][jj][q] = 0.f;

    const unsigned char* aHbase = g_cAhi + (size_t)tn * NKC * ABLK;
    const unsigned char* aLbase = g_cAlo + (size_t)tn * NKC * ABLK;

    for (int kc = 0; kc < NKC; ++kc) {
        __syncthreads();   // protect prior chunk's smem reads
        // coop-load B chunk (12 jtiles x 4 tk, hi+lo). 1KB contiguous per jtile.
        #pragma unroll
        for (int r = 0; r < 3; ++r) {
            int i = tid + r * 256;             // uint4 index, 768 total per precision
            int jj = i >> 6;                   // 64 x 16B = 1KB per jtile
            int rest = (i & 63) * 16;
            size_t src = (size_t)(((jh * 12 + jj) * 48 + kc * 4) * 256) + rest;
            ((uint4*)sBh)[i] = *(const uint4*)(g_Bhi + src);
            ((uint4*)sBl)[i] = *(const uint4*)(g_Blo + src);
        }
        __syncthreads();
        #pragma unroll
        for (int tkL = 0; tkL < 4; ++tkL) {
            uint32_t inner = (uint32_t)(tkL * 512 + lane * 16);
            uint4 ah[2], al[2];
            #pragma unroll
            for (int mi = 0; mi < 2; mi++) {
                uint32_t off = (uint32_t)kc * ABLK + (uint32_t)(mw * 2 + mi) * 2048 + inner;
                ah[mi] = *(const uint4*)(aHbase + off);
                al[mi] = *(const uint4*)(aLbase + off);
            }
            #pragma unroll
            for (int jj = 0; jj < 6; jj++) {
                uint32_t boff = (uint32_t)((jloc + jj) * 1024 + tkL * 256 + lane * 8);
                uint2 bh = *(const uint2*)(sBh + boff);
                uint2 bl = *(const uint2*)(sBl + boff);
                #pragma unroll
                for (int mi = 0; mi < 2; mi++) {
                    mma16816(acc[mi][jj], (const uint32_t*)&ah[mi], (const uint32_t*)&bh);
                    mma16816(acc[mi][jj], (const uint32_t*)&al[mi], (const uint32_t*)&bh);
                    mma16816(acc[mi][jj], (const uint32_t*)&ah[mi], (const uint32_t*)&bl);
                }
            }
        }
    }

    int g = lane >> 2, tig = lane & 3;
    int jbase = jh * 12 + jloc;
    #pragma unroll
    for (int mi = 0; mi < 2; mi++) {
        int row0 = tn * 128 + (mw * 2 + mi) * 16 + g;
        #pragma unroll
        for (int jj = 0; jj < 6; jj++) {
            int col = (jbase + jj) * 8 + tig * 2;
            if (col < JTOT) {
                Cout[(size_t)row0 * JTOT + col] = acc[mi][jj][0];
                Cout[(size_t)(row0 + 8) * JTOT + col] = acc[mi][jj][2];
                if (col + 1 < JTOT) {
                    Cout[(size_t)row0 * JTOT + col + 1] = acc[mi][jj][1];
                    Cout[(size_t)(row0 + 8) * JTOT + col + 1] = acc[mi][jj][3];
                }
            }
        }
    }
}

// per-pixel head
__global__ void k_head(const float* __restrict__ logits, const int* __restrict__ gt,
                       const float* __restrict__ mg, const float* __restrict__ mb,
                       float* __restrict__ out_seg) {
    __shared__ float rows[8][192];
    int warp = threadIdx.x >> 5, lane = threadIdx.x & 31;
    int n = blockIdx.x * 8 + warp;
    const float* lr = logits + (size_t)n * JTOT;
    #pragma unroll
    for (int i = 0; i < 6; i++) {
        int j = lane + 32 * i;
        if (j < JTOT) rows[warp][j] = lr[j];
    }
    __syncwarp();
    float mx = -FLT_MAX;
    if (lane < KCLS) {
        #pragma unroll
        for (int m = 0; m < MPROT; m++) mx = fmaxf(mx, rows[warp][lane * MPROT + m]);
    }
    float xv = (lane < KCLS) ? mx : 0.f;
    float s = xv, s2 = xv * xv;
    #pragma unroll
    for (int off = 16; off; off >>= 1) {
        s  += __shfl_xor_sync(0xffffffffu, s, off);
        s2 += __shfl_xor_sync(0xffffffffu, s2, off);
    }
    float mu = s * (1.f / KCLS);
    float var = s2 * (1.f / KCLS) - mu * mu;
    float isd = 1.f / sqrtf(var + 1e-5f);
    float o = -FLT_MAX;
    if (lane < KCLS) {
        o = (mx - mu) * isd * __ldg(&mg[lane]) + __ldg(&mb[lane]);
        int b = n >> 15, h = (n >> 8) & 127, w = n & 255;
        out_seg[(((size_t)b * KCLS + lane) * 128 + h) * WID + w] = o;
    }
    float bv = o; int bi = lane;
    #pragma unroll
    for (int off = 16; off; off >>= 1) {
        float ov = __shfl_xor_sync(0xffffffffu, bv, off);
        int   oi = __shfl_xor_sync(0xffffffffu, bi, off);
        if (ov > bv || (ov == bv && oi < bi)) { bv = ov; bi = oi; }
    }
    if (lane == 0) g_corr[n] = (bi == gt[n]) ? 1 : 0;
}

__global__ void k_sh_init(const float* __restrict__ logits, const int* __restrict__ gt) {
    __shared__ float sS[KCLS];
    __shared__ int sB[KCLS];
    __shared__ float sR[JTOT];
    int t = threadIdx.x;
    if (t < KCLS) { sS[t] = 0.f; sB[t] = 0; }
    if (t < JTOT) sR[t] = 0.f;
    __syncthreads();
    int n = blockIdx.x * blockDim.x + t;
    int k = gt[n];
    const float* lr = logits + (size_t)n * JTOT + k * MPROT;
    float v[MPROT]; float sum = 0.f;
    #pragma unroll
    for (int m = 0; m < MPROT; m++) { v[m] = expf(lr[m] * 20.f); sum += v[m]; }
    atomicAdd(&sS[k], sum);
    atomicAdd(&sB[k], 1);
    #pragma unroll
    for (int m = 0; m < MPROT; m++) atomicAdd(&sR[k * MPROT + m], v[m]);
    g_b[n] = 1.f;
    __syncthreads();
    if (t < KCLS) { atomicAdd(&g_S[t], sS[t]); atomicAdd(&g_Bk[t], sB[t]); }
    if (t < JTOT) atomicAdd(&g_R[t], sR[t]);
}

__global__ void k_a(int t) {
    int j = threadIdx.x;
    if (j >= JTOT) return;
    int k = j / MPROT;
    float ap = (t == 0) ? 1.f / fmaxf(g_S[k], 1e-12f) : g_a[j];
    float rowsum = ap * g_R[t * JTOT + j];
    g_a[j] = ap / (fmaxf(rowsum, 1e-12f) * (float)MPROT);
}

__global__ void k_bR(const float* __restrict__ logits, const int* __restrict__ gt, int slot) {
    __shared__ float sR[JTOT];
    int t = threadIdx.x;
    if (t < JTOT) sR[t] = 0.f;
    __syncthreads();
    int n = blockIdx.x * blockDim.x + t;
    int k = gt[n];
    const float* lr = logits + (size_t)n * JTOT + k * MPROT;
    float v[MPROT]; float s = 0.f;
    #pragma unroll
    for (int m = 0; m < MPROT; m++) {
        v[m] = expf(lr[m] * 20.f);
        s = fmaf(v[m], __ldg(&g_a[k * MPROT + m]), s);
    }
    float b = g_b[n];
    float col = b * s;
    float Bk = fmaxf((float)g_Bk[k], 1.f);
    float nb = (col > 0.f) ? (b / fmaxf(col, 1e-12f)) / Bk : 0.f;
    g_b[n] = nb;
    #pragma unroll
    for (int m = 0; m < MPROT; m++) atomicAdd(&sR[k * MPROT + m], v[m] * nb);
    __syncthreads();
    if (t < JTOT) atomicAdd(&g_R[slot * JTOT + t], sR[t]);
}

__global__ void k_final(const float* __restrict__ logits, const int* __restrict__ gt,
                        float* __restrict__ target) {
    int n = blockIdx.x * blockDim.x + threadIdx.x;
    int k = gt[n];
    const float* lr = logits + (size_t)n * JTOT + k * MPROT;
    float best = -FLT_MAX; int bm = 0;
    #pragma unroll
    for (int m = 0; m < MPROT; m++) {
        float q = expf(lr[m] * 20.f) * __ldg(&g_a[k * MPROT + m]);
        if (q > best) { best = q; bm = m; }
    }
    g_m[n] = (unsigned char)bm;
    target[n] = (float)(bm + MPROT * k);
}

// accumulate f over correct pixels, reconstructing _c from A hi/lo fragments
__global__ void k_faccum(const int* __restrict__ gt) {
    int t = threadIdx.x;
    int base = blockIdx.x * 32;
    for (int p = 0; p < 32; p++) {
        int n = base + p;
        if (!g_corr[n]) continue;
        int j = gt[n] * MPROT + g_m[n];
        if (t == 0) atomicAdd(&g_cnt[j], 1);
        int tn = n >> 7, nl = n & 127;
        for (int d = t; d < DIMC; d += blockDim.x) {
            int kc = d >> 6, dl = d & 63;
            size_t tb = ((size_t)tn * NKC + kc) * ABLK;
            uint32_t off = afrag_off(nl, dl);
            float v = __bfloat162float(*(const __nv_bfloat16*)(g_cAhi + tb + off))
                    + __bfloat162float(*(const __nv_bfloat16*)(g_cAlo + tb + off));
            atomicAdd(&g_f[j * DIMC + d], v);
        }
    }
}

__global__ void k_proto_out(float* __restrict__ outp) {
    __shared__ float red[256];
    __shared__ float cand[DIMC];
    int j = blockIdx.x, t = threadIdx.x, k = j / MPROT;
    int cnt = g_cnt[j];
    int rs = 0;
    #pragma unroll
    for (int m = 0; m < MPROT; m++) rs += g_cnt[k * MPROT + m];
    bool upd = (cnt > 0) && (rs > 0);
    float ss = 0.f;
    for (int d = t; d < DIMC; d += 256) { float fv = g_f[j * DIMC + d]; ss += fv * fv; }
    float fn = sqrtf(block_reduce_256(ss, red));
    float finv = 1.f / fmaxf(fn, 1e-12f);
    float ss2 = 0.f;
    for (int d = t; d < DIMC; d += 256) {
        float p = g_Pn[j * DIMC + d];
        float cv = upd ? (0.999f * p + 0.001f * (g_f[j * DIMC + d] * finv)) : p;
        cand[d] = cv; ss2 += cv * cv;
    }
    float n2 = fmaxf(sqrtf(block_reduce_256(ss2, red)), 1e-12f);
    float inv2 = 1.f / n2;
    __syncthreads();
    for (int d = t; d < DIMC; d += 256) outp[j * DIMC + d] = cand[d] * inv2;
}

// ---------------- launch ----------------
extern "C" void kernel_launch(void* const* d_in, const int* in_sizes, int n_in,
                              void* d_out, int out_size) {
    const float* c  = (const float*)d_in[0];
    const int*   gt = (const int*)d_in[1];
    const float* P  = (const float*)d_in[2];
    const float* fg = (const float*)d_in[3];
    const float* fb = (const float*)d_in[4];
    const float* mg = (const float*)d_in[5];
    const float* mb = (const float*)d_in[6];

    float* out      = (float*)d_out;
    float* out_seg  = out;
    float* logits   = out + 2490368;
    float* target   = out + 2490368 + 24903680;
    float* pnew     = target + NPIX;

    k_zero<<<535, 256>>>();
    k_prep_scal<<<1, 256>>>(fg, fb);
    k_prep_protos<<<JTOT, 256>>>(P);
    k_stats<<<NPIX / 256, 256>>>(c, fg, fb);
    k_normsplit<<<NTILE * NKC, 256>>>(c, fg, fb);
    k_gemm_mma<<<NTILE * 2, 256>>>(logits);
    k_head<<<NPIX / 8, 256>>>(logits, gt, mg, mb, out_seg);
    k_sh_init<<<NPIX / 256, 256>>>(logits, gt);
    k_a<<<1, 192>>>(0);
    k_bR<<<NPIX / 256, 256>>>(logits, gt, 1);
    k_a<<<1, 192>>>(1);
    k_bR<<<NPIX / 256, 256>>>(logits, gt, 2);
    k_a<<<1, 192>>>(2);
    k_final<<<NPIX / 256, 256>>>(logits, gt, target);
    k_faccum<<<NPIX / 32, 256>>>(gt);
    k_proto_out<<<JTOT, 256>>>(pnew);
}